// round 11
// baseline (speedup 1.0000x reference)
#include <cuda_runtime.h>
#include <cuda_bf16.h>
#include <math.h>
#include <cstdint>

#define S_LEN 8192
#define DIM   1024
#define NH    16
#define HD    64
#define WIN   512

// ---------------- scratch (allocation-free rule: device globals) ----------
__device__ __align__(256) __nv_bfloat16 g_xhi[S_LEN * DIM];
__device__ __align__(256) __nv_bfloat16 g_xlo[S_LEN * DIM];
__device__ __align__(256) __nv_bfloat16 g_whi[4 * DIM * DIM];
__device__ __align__(256) __nv_bfloat16 g_wlo[4 * DIM * DIM];
__device__ __align__(256) __nv_bfloat16 g_qhi[S_LEN * DIM];
__device__ __align__(256) __nv_bfloat16 g_qlo[S_LEN * DIM];
__device__ __align__(256) __nv_bfloat16 g_khi[S_LEN * DIM];
__device__ __align__(256) __nv_bfloat16 g_klo[S_LEN * DIM];
__device__ __align__(256) __nv_bfloat16 g_vhi[S_LEN * DIM];
__device__ __align__(256) __nv_bfloat16 g_vlo[S_LEN * DIM];
__device__ __align__(256) __nv_bfloat16 g_ohi[S_LEN * DIM];
__device__ __align__(256) __nv_bfloat16 g_olo[S_LEN * DIM];

// ---------------- fused fp32 -> bf16 hi/lo split (x + 4 weights) -----------
#define XN4 (S_LEN * DIM / 4)
#define WN4 (DIM * DIM / 4)
__global__ void split_all_kernel(const float* __restrict__ x,
                                 const float* __restrict__ Wq,
                                 const float* __restrict__ Wk,
                                 const float* __restrict__ Wv,
                                 const float* __restrict__ Wo,
                                 __nv_bfloat16* __restrict__ xhi,
                                 __nv_bfloat16* __restrict__ xlo,
                                 __nv_bfloat16* __restrict__ whi,
                                 __nv_bfloat16* __restrict__ wlo)
{
    int i = blockIdx.x * blockDim.x + threadIdx.x;
    const float* src;
    __nv_bfloat16 *hi, *lo;
    int idx;
    if (i < XN4) {
        src = x; hi = xhi; lo = xlo; idx = i;
    } else {
        int j = i - XN4;
        if (j >= 4 * WN4) return;
        int w = j / WN4;
        idx = j - w * WN4;
        src = (w == 0) ? Wq : (w == 1) ? Wk : (w == 2) ? Wv : Wo;
        hi = whi + (size_t)w * DIM * DIM;
        lo = wlo + (size_t)w * DIM * DIM;
    }
    float4 v = ((const float4*)src)[idx];
    __nv_bfloat16 h0 = __float2bfloat16(v.x);
    __nv_bfloat16 h1 = __float2bfloat16(v.y);
    __nv_bfloat16 h2 = __float2bfloat16(v.z);
    __nv_bfloat16 h3 = __float2bfloat16(v.w);
    __nv_bfloat16 l0 = __float2bfloat16(v.x - __bfloat162float(h0));
    __nv_bfloat16 l1 = __float2bfloat16(v.y - __bfloat162float(h1));
    __nv_bfloat16 l2 = __float2bfloat16(v.z - __bfloat162float(h2));
    __nv_bfloat16 l3 = __float2bfloat16(v.w - __bfloat162float(h3));
    uint2 uh, ul;
    uh.x = (uint32_t)__bfloat16_as_ushort(h0) | ((uint32_t)__bfloat16_as_ushort(h1) << 16);
    uh.y = (uint32_t)__bfloat16_as_ushort(h2) | ((uint32_t)__bfloat16_as_ushort(h3) << 16);
    ul.x = (uint32_t)__bfloat16_as_ushort(l0) | ((uint32_t)__bfloat16_as_ushort(l1) << 16);
    ul.y = (uint32_t)__bfloat16_as_ushort(l2) | ((uint32_t)__bfloat16_as_ushort(l3) << 16);
    ((uint2*)hi)[idx] = uh;
    ((uint2*)lo)[idx] = ul;
}

// ---------------- HMMA helpers --------------------------------------------
__device__ __forceinline__ uint32_t smem_u32(const void* p) {
    uint32_t a;
    asm("{ .reg .u64 t; cvta.to.shared.u64 t, %1; cvt.u32.u64 %0, t; }"
        : "=r"(a) : "l"(p));
    return a;
}
__device__ __forceinline__ void ldsm_x4(uint32_t* r, uint32_t saddr) {
    asm volatile("ldmatrix.sync.aligned.m8n8.x4.shared.b16 {%0,%1,%2,%3}, [%4];"
                 : "=r"(r[0]), "=r"(r[1]), "=r"(r[2]), "=r"(r[3]) : "r"(saddr));
}
__device__ __forceinline__ void ldsm_x4_trans(uint32_t* r, uint32_t saddr) {
    asm volatile("ldmatrix.sync.aligned.m8n8.x4.trans.shared.b16 {%0,%1,%2,%3}, [%4];"
                 : "=r"(r[0]), "=r"(r[1]), "=r"(r[2]), "=r"(r[3]) : "r"(saddr));
}
__device__ __forceinline__ void mma_bf16(float* c, const uint32_t* a,
                                         uint32_t b0, uint32_t b1) {
    asm volatile(
        "mma.sync.aligned.m16n8k16.row.col.f32.bf16.bf16.f32 "
        "{%0,%1,%2,%3}, {%4,%5,%6,%7}, {%8,%9}, {%0,%1,%2,%3};"
        : "+f"(c[0]), "+f"(c[1]), "+f"(c[2]), "+f"(c[3])
        : "r"(a[0]), "r"(a[1]), "r"(a[2]), "r"(a[3]), "r"(b0), "r"(b1));
}
#define CP_ASYNC16(saddr, gptr) \
    asm volatile("cp.async.ca.shared.global [%0], [%1], 16;" \
                 :: "r"(saddr), "l"(gptr))
#define CP_COMMIT()  asm volatile("cp.async.commit_group;" ::: "memory")
#define CP_WAIT(n)   asm volatile("cp.async.wait_group %0;" :: "n"(n) : "memory")

// pack two floats -> bf16x2 word
__device__ __forceinline__ uint32_t pack_bf2(float x, float y) {
    __nv_bfloat16 bx = __float2bfloat16(x), by = __float2bfloat16(y);
    return (uint32_t)__bfloat16_as_ushort(bx) |
           ((uint32_t)__bfloat16_as_ushort(by) << 16);
}
__device__ __forceinline__ void split_pair(float x, float y,
                                           uint32_t& hw, uint32_t& lw) {
    __nv_bfloat16 hx = __float2bfloat16(x), hy = __float2bfloat16(y);
    hw = (uint32_t)__bfloat16_as_ushort(hx) |
         ((uint32_t)__bfloat16_as_ushort(hy) << 16);
    lw = pack_bf2(x - __bfloat162float(hx), y - __bfloat162float(hy));
}

// ---------------- HMMA split-fp32 GEMM NT, 4-stage cp.async pipeline -------
// FS=true: epilogue applies RoPE (z<2) and writes bf16 hi/lo (fused split).
// FS=false: epilogue writes fp32 C0.
#define SKB   40
#define TILEB (128 * SKB * 2)
#define STAGEB (4 * TILEB)               // 40960 B
#define NSTAGE 4
#define GEMM_SMEM (NSTAGE * STAGEB)      // 163840 B
#define NCHUNK (DIM / 32)

template <bool FS>
__global__ __launch_bounds__(256)
void gemm_hmma(const __nv_bfloat16* __restrict__ Ahi,
               const __nv_bfloat16* __restrict__ Alo,
               const __nv_bfloat16* __restrict__ Bhi_all,
               const __nv_bfloat16* __restrict__ Blo_all,
               float* __restrict__ C0,
               __nv_bfloat16* __restrict__ H0, __nv_bfloat16* __restrict__ L0,
               __nv_bfloat16* __restrict__ H1, __nv_bfloat16* __restrict__ L1,
               __nv_bfloat16* __restrict__ H2, __nv_bfloat16* __restrict__ L2)
{
    extern __shared__ char smem[];
    const uint32_t sb = smem_u32(smem);
    const int t    = threadIdx.x;
    const int wid  = t >> 5;
    const int lane = t & 31;
    const int bm = blockIdx.y * 128;
    const int bn = blockIdx.x * 128;
    const int z  = blockIdx.z;
    const __nv_bfloat16* bhi = Bhi_all + (size_t)z * DIM * DIM;
    const __nv_bfloat16* blo = Blo_all + (size_t)z * DIM * DIM;

    const int wm = (wid >> 2) * 64;
    const int wn = (wid & 3) * 32;

    float acc[4][4][4];
#pragma unroll
    for (int i = 0; i < 4; i++)
#pragma unroll
        for (int j = 0; j < 4; j++)
#pragma unroll
            for (int r = 0; r < 4; r++) acc[i][j][r] = 0.0f;

    auto issue_chunk = [&](int kc, int stage) {
        const uint32_t sbase = sb + stage * STAGEB;
#pragma unroll
        for (int i = 0; i < 8; i++) {
            int id   = t + 256 * i;
            int tile = id >> 9;
            int w    = id & 511;
            int row  = w >> 2;
            int cg   = (w & 3) * 8;
            uint32_t so = sbase + tile * TILEB + (uint32_t)(row * SKB + cg) * 2;
            const __nv_bfloat16* gp;
            if (tile == 0)      gp = Ahi + (size_t)(bm + row) * DIM + kc + cg;
            else if (tile == 1) gp = Alo + (size_t)(bm + row) * DIM + kc + cg;
            else if (tile == 2) gp = bhi + (size_t)(bn + row) * DIM + kc + cg;
            else                gp = blo + (size_t)(bn + row) * DIM + kc + cg;
            CP_ASYNC16(so, gp);
        }
        CP_COMMIT();
    };

    // Prologue: fill 3 stages (NSTAGE-1 in flight)
    issue_chunk(0, 0);
    issue_chunk(32, 1);
    issue_chunk(64, 2);

    const int lrow = lane & 7;
    const int seg  = lane >> 3;

    for (int c = 0; c < NCHUNK; c++) {
        // One commit per iteration (empty at tail) => wait(2) proves the
        // 3rd-newest group — chunk c — is complete.
        CP_WAIT(2);
        __syncthreads();
        if (c + 3 < NCHUNK) issue_chunk((c + 3) * 32, (c + 3) & (NSTAGE - 1));
        else                CP_COMMIT();

        const uint32_t stg = sb + (c & (NSTAGE - 1)) * STAGEB;
#pragma unroll
        for (int ks = 0; ks < 32; ks += 16) {
            uint32_t bh[2][4], bl[2][4];
#pragma unroll
            for (int p = 0; p < 2; p++) {
                int br = wn + p * 16 + (seg >> 1) * 8 + lrow;
                int bc = ks + (seg & 1) * 8;
                uint32_t off = (uint32_t)(br * SKB + bc) * 2;
                ldsm_x4(bh[p], stg + 2 * TILEB + off);
                ldsm_x4(bl[p], stg + 3 * TILEB + off);
            }
#pragma unroll
            for (int mt = 0; mt < 4; mt++) {
                int ar = wm + mt * 16 + (seg & 1) * 8 + lrow;
                int ac = ks + (seg >> 1) * 8;
                uint32_t off = (uint32_t)(ar * SKB + ac) * 2;
                uint32_t ah[4], al[4];
                ldsm_x4(ah, stg + 0 * TILEB + off);
                ldsm_x4(al, stg + 1 * TILEB + off);
#pragma unroll
                for (int nt = 0; nt < 4; nt++) {
                    int p = nt >> 1, q = (nt & 1) * 2;
                    mma_bf16(acc[mt][nt], ah, bh[p][q], bh[p][q + 1]);
                    mma_bf16(acc[mt][nt], ah, bl[p][q], bl[p][q + 1]);
                    mma_bf16(acc[mt][nt], al, bh[p][q], bh[p][q + 1]);
                }
            }
        }
    }

    const int trow = lane >> 2;
    const int tcol = (lane & 3) * 2;

    if (!FS) {
#pragma unroll
        for (int mt = 0; mt < 4; mt++) {
#pragma unroll
            for (int nt = 0; nt < 4; nt++) {
                size_t r0 = (size_t)(bm + wm + mt * 16 + trow);
                size_t cc = (size_t)(bn + wn + nt * 8 + tcol);
                *(float2*)(C0 + r0 * DIM + cc) =
                    make_float2(acc[mt][nt][0], acc[mt][nt][1]);
                *(float2*)(C0 + (r0 + 8) * DIM + cc) =
                    make_float2(acc[mt][nt][2], acc[mt][nt][3]);
            }
        }
    } else {
        __nv_bfloat16* Hp = (z == 0) ? H0 : (z == 1 ? H1 : H2);
        __nv_bfloat16* Lp = (z == 0) ? L0 : (z == 1 ? L1 : L2);
        const bool rope = (z != 2);
#pragma unroll
        for (int nt = 0; nt < 4; nt++) {
            int cc = bn + wn + nt * 8 + tcol;
            float invf = 0.0f;
            if (rope) {
                int j = (cc & 63) >> 1;
                invf = 1.0f / powf(10000.0f, (float)(2 * j) * (1.0f / 64.0f));
            }
#pragma unroll
            for (int mt = 0; mt < 4; mt++) {
                int r0 = bm + wm + mt * 16 + trow;
                float a0 = acc[mt][nt][0], a1 = acc[mt][nt][1];
                float a2 = acc[mt][nt][2], a3 = acc[mt][nt][3];
                if (rope) {
                    float s0, c0, s1, c1;
                    sincosf((float)r0 * invf, &s0, &c0);
                    sincosf((float)(r0 + 8) * invf, &s1, &c1);
                    float n0 = a0 * c0 - a1 * s0;
                    float n1 = a0 * s0 + a1 * c0;
                    float n2 = a2 * c1 - a3 * s1;
                    float n3 = a2 * s1 + a3 * c1;
                    a0 = n0; a1 = n1; a2 = n2; a3 = n3;
                }
                uint32_t hw0, lw0, hw1, lw1;
                split_pair(a0, a1, hw0, lw0);
                split_pair(a2, a3, hw1, lw1);
                size_t base0 = (size_t)r0 * DIM + cc;
                size_t base1 = (size_t)(r0 + 8) * DIM + cc;
                *(uint32_t*)(Hp + base0) = hw0;
                *(uint32_t*)(Lp + base0) = lw0;
                *(uint32_t*)(Hp + base1) = hw1;
                *(uint32_t*)(Lp + base1) = lw1;
            }
        }
    }
}

// ---------------- HMMA split-bf16 sliding-window flash attention -----------
#define SKD 72
#define ATN_Q_HI 0
#define ATN_Q_LO 18432
#define ATN_K_HI 36864
#define ATN_K_LO 55296
#define ATN_V_HI 73728
#define ATN_V_LO 92160
#define ATN_SMEM 110592

__global__ __launch_bounds__(256, 1) void attn_hmma(
    const __nv_bfloat16* __restrict__ qhi, const __nv_bfloat16* __restrict__ qlo,
    const __nv_bfloat16* __restrict__ khi, const __nv_bfloat16* __restrict__ klo,
    const __nv_bfloat16* __restrict__ vhi, const __nv_bfloat16* __restrict__ vlo,
    __nv_bfloat16* __restrict__ ohi, __nv_bfloat16* __restrict__ olo)
{
    extern __shared__ char sms[];
    const uint32_t sb = smem_u32(sms);
    const int t = threadIdx.x;
    const int lane = t & 31;
    const int wid  = t >> 5;
    const int h  = blockIdx.y;
    const int qs = blockIdx.x * 128;
    const int lrow = lane & 7;
    const int seg  = lane >> 3;

#pragma unroll
    for (int i = 0; i < 4; i++) {
        int f = i * 256 + t;
        int r = f >> 3, cg = (f & 7) * 8;
        uint32_t so = (uint32_t)(r * SKD + cg) * 2;
        size_t g = (size_t)(qs + r) * DIM + h * HD + cg;
        *(uint4*)(sms + ATN_Q_HI + so) = *(const uint4*)(qhi + g);
        *(uint4*)(sms + ATN_Q_LO + so) = *(const uint4*)(qlo + g);
    }
    __syncthreads();

    uint32_t aQh[4][4], aQl[4][4];
    {
        int ar = wid * 16 + (seg & 1) * 8 + lrow;
#pragma unroll
        for (int ks = 0; ks < 4; ks++) {
            int ac = ks * 16 + (seg >> 1) * 8;
            uint32_t off = (uint32_t)(ar * SKD + ac) * 2;
            ldsm_x4(aQh[ks], sb + ATN_Q_HI + off);
            ldsm_x4(aQl[ks], sb + ATN_Q_LO + off);
        }
    }

    float m0 = -1e30f, m1 = -1e30f, l0 = 0.0f, l1 = 0.0f;
    float oa[8][4];
#pragma unroll
    for (int i = 0; i < 8; i++)
#pragma unroll
        for (int j = 0; j < 4; j++) oa[i][j] = 0.0f;

    const int r0 = wid * 16 + (lane >> 2);
    const int qg0 = qs + r0;
    const int qg1 = qg0 + 8;

    int kt0 = qs - WIN;
    if (kt0 < 0) kt0 = 0;

    for (int kt = kt0; kt <= qs; kt += 128) {
        __syncthreads();
#pragma unroll
        for (int i = 0; i < 4; i++) {
            int f = i * 256 + t;
            int r = f >> 3, cg = (f & 7) * 8;
            uint32_t so = (uint32_t)(r * SKD + cg) * 2;
            size_t g = (size_t)(kt + r) * DIM + h * HD + cg;
            *(uint4*)(sms + ATN_K_HI + so) = *(const uint4*)(khi + g);
            *(uint4*)(sms + ATN_K_LO + so) = *(const uint4*)(klo + g);
            *(uint4*)(sms + ATN_V_HI + so) = *(const uint4*)(vhi + g);
            *(uint4*)(sms + ATN_V_LO + so) = *(const uint4*)(vlo + g);
        }
        __syncthreads();

        float sc[16][4];
#pragma unroll
        for (int i = 0; i < 16; i++)
#pragma unroll
            for (int j = 0; j < 4; j++) sc[i][j] = 0.0f;

#pragma unroll
        for (int ks = 0; ks < 4; ks++) {
#pragma unroll
            for (int bp = 0; bp < 8; bp++) {
                uint32_t bh[4], bl[4];
                int br = bp * 16 + (seg >> 1) * 8 + lrow;
                int bc = ks * 16 + (seg & 1) * 8;
                uint32_t off = (uint32_t)(br * SKD + bc) * 2;
                ldsm_x4(bh, sb + ATN_K_HI + off);
                ldsm_x4(bl, sb + ATN_K_LO + off);
                mma_bf16(sc[2 * bp],     aQh[ks], bh[0], bh[1]);
                mma_bf16(sc[2 * bp],     aQh[ks], bl[0], bl[1]);
                mma_bf16(sc[2 * bp],     aQl[ks], bh[0], bh[1]);
                mma_bf16(sc[2 * bp + 1], aQh[ks], bh[2], bh[3]);
                mma_bf16(sc[2 * bp + 1], aQh[ks], bl[2], bl[3]);
                mma_bf16(sc[2 * bp + 1], aQl[ks], bh[2], bh[3]);
            }
        }

        float nm0 = m0, nm1 = m1;
#pragma unroll
        for (int nt = 0; nt < 16; nt++) {
            int kg = kt + nt * 8 + (lane & 3) * 2;
            sc[nt][0] = (kg     <= qg0 && kg     > qg0 - WIN) ? sc[nt][0] * 0.125f : -1e30f;
            sc[nt][1] = (kg + 1 <= qg0 && kg + 1 > qg0 - WIN) ? sc[nt][1] * 0.125f : -1e30f;
            sc[nt][2] = (kg     <= qg1 && kg     > qg1 - WIN) ? sc[nt][2] * 0.125f : -1e30f;
            sc[nt][3] = (kg + 1 <= qg1 && kg + 1 > qg1 - WIN) ? sc[nt][3] * 0.125f : -1e30f;
            nm0 = fmaxf(nm0, fmaxf(sc[nt][0], sc[nt][1]));
            nm1 = fmaxf(nm1, fmaxf(sc[nt][2], sc[nt][3]));
        }
        nm0 = fmaxf(nm0, __shfl_xor_sync(0xffffffffu, nm0, 1));
        nm0 = fmaxf(nm0, __shfl_xor_sync(0xffffffffu, nm0, 2));
        nm1 = fmaxf(nm1, __shfl_xor_sync(0xffffffffu, nm1, 1));
        nm1 = fmaxf(nm1, __shfl_xor_sync(0xffffffffu, nm1, 2));

        float al0 = __expf(m0 - nm0);
        float al1 = __expf(m1 - nm1);
        m0 = nm0; m1 = nm1;

        float rs0 = 0.0f, rs1 = 0.0f;
#pragma unroll
        for (int nt = 0; nt < 16; nt++) {
            float p0 = (sc[nt][0] > -1e29f) ? __expf(sc[nt][0] - m0) : 0.0f;
            float p1 = (sc[nt][1] > -1e29f) ? __expf(sc[nt][1] - m0) : 0.0f;
            float p2 = (sc[nt][2] > -1e29f) ? __expf(sc[nt][2] - m1) : 0.0f;
            float p3 = (sc[nt][3] > -1e29f) ? __expf(sc[nt][3] - m1) : 0.0f;
            sc[nt][0] = p0; sc[nt][1] = p1; sc[nt][2] = p2; sc[nt][3] = p3;
            rs0 += p0 + p1;
            rs1 += p2 + p3;
        }
        rs0 += __shfl_xor_sync(0xffffffffu, rs0, 1);
        rs0 += __shfl_xor_sync(0xffffffffu, rs0, 2);
        rs1 += __shfl_xor_sync(0xffffffffu, rs1, 1);
        rs1 += __shfl_xor_sync(0xffffffffu, rs1, 2);
        l0 = l0 * al0 + rs0;
        l1 = l1 * al1 + rs1;

#pragma unroll
        for (int i = 0; i < 8; i++) {
            oa[i][0] *= al0; oa[i][1] *= al0;
            oa[i][2] *= al1; oa[i][3] *= al1;
        }

#pragma unroll
        for (int j = 0; j < 8; j++) {
            float p00 = sc[2 * j][0],     p01 = sc[2 * j][1];
            float p02 = sc[2 * j][2],     p03 = sc[2 * j][3];
            float p10 = sc[2 * j + 1][0], p11 = sc[2 * j + 1][1];
            float p12 = sc[2 * j + 1][2], p13 = sc[2 * j + 1][3];
            uint32_t pah[4], pal[4];
            split_pair(p00, p01, pah[0], pal[0]);
            split_pair(p02, p03, pah[1], pal[1]);
            split_pair(p10, p11, pah[2], pal[2]);
            split_pair(p12, p13, pah[3], pal[3]);
#pragma unroll
            for (int dp = 0; dp < 4; dp++) {
                uint32_t bh[4], bl[4];
                int kk = j * 16 + (seg & 1) * 8 + lrow;
                int nn = dp * 16 + (seg >> 1) * 8;
                uint32_t off = (uint32_t)(kk * SKD + nn) * 2;
                ldsm_x4_trans(bh, sb + ATN_V_HI + off);
                ldsm_x4_trans(bl, sb + ATN_V_LO + off);
                mma_bf16(oa[dp * 2],     pah, bh[0], bh[1]);
                mma_bf16(oa[dp * 2],     pah, bl[0], bl[1]);
                mma_bf16(oa[dp * 2],     pal, bh[0], bh[1]);
                mma_bf16(oa[dp * 2 + 1], pah, bh[2], bh[3]);
                mma_bf16(oa[dp * 2 + 1], pah, bl[2], bl[3]);
                mma_bf16(oa[dp * 2 + 1], pal, bh[2], bh[3]);
            }
        }
    }

    float inv0 = 1.0f / l0;
    float inv1 = 1.0f / l1;
    const int tcol = (lane & 3) * 2;
#pragma unroll
    for (int dt = 0; dt < 8; dt++) {
        size_t c = (size_t)(h * HD + dt * 8 + tcol);
        uint32_t hw0, lw0, hw1, lw1;
        split_pair(oa[dt][0] * inv0, oa[dt][1] * inv0, hw0, lw0);
        split_pair(oa[dt][2] * inv1, oa[dt][3] * inv1, hw1, lw1);
        size_t b0 = (size_t)qg0 * DIM + c;
        size_t b1 = (size_t)qg1 * DIM + c;
        *(uint32_t*)(ohi + b0) = hw0;
        *(uint32_t*)(olo + b0) = lw0;
        *(uint32_t*)(ohi + b1) = hw1;
        *(uint32_t*)(olo + b1) = lw1;
    }
}

// ---------------------------------------------------------------------------
extern "C" void kernel_launch(void* const* d_in, const int* in_sizes, int n_in,
                              void* d_out, int out_size)
{
    const float* x  = (const float*)d_in[0];
    const float* Wq = (const float*)d_in[1];
    const float* Wk = (const float*)d_in[2];
    const float* Wv = (const float*)d_in[3];
    const float* Wo = (const float*)d_in[4];
    float* out = (float*)d_out;

    __nv_bfloat16 *xhi, *xlo, *whi, *wlo;
    __nv_bfloat16 *qhi, *qlo, *khi, *klo, *vhi, *vlo, *ohi, *olo;
    cudaGetSymbolAddress((void**)&xhi, g_xhi);
    cudaGetSymbolAddress((void**)&xlo, g_xlo);
    cudaGetSymbolAddress((void**)&whi, g_whi);
    cudaGetSymbolAddress((void**)&wlo, g_wlo);
    cudaGetSymbolAddress((void**)&qhi, g_qhi);
    cudaGetSymbolAddress((void**)&qlo, g_qlo);
    cudaGetSymbolAddress((void**)&khi, g_khi);
    cudaGetSymbolAddress((void**)&klo, g_klo);
    cudaGetSymbolAddress((void**)&vhi, g_vhi);
    cudaGetSymbolAddress((void**)&vlo, g_vlo);
    cudaGetSymbolAddress((void**)&ohi, g_ohi);
    cudaGetSymbolAddress((void**)&olo, g_olo);

    cudaFuncSetAttribute(gemm_hmma<true>,
                         cudaFuncAttributeMaxDynamicSharedMemorySize, GEMM_SMEM);
    cudaFuncSetAttribute(gemm_hmma<false>,
                         cudaFuncAttributeMaxDynamicSharedMemorySize, GEMM_SMEM);
    cudaFuncSetAttribute(attn_hmma,
                         cudaFuncAttributeMaxDynamicSharedMemorySize, ATN_SMEM);

    // 1) Fused split of x + all 4 weights into bf16 hi/lo (single launch)
    {
        int total = XN4 + 4 * WN4;
        split_all_kernel<<<(total + 255) / 256, 256>>>(
            x, Wq, Wk, Wv, Wo, xhi, xlo, whi, wlo);
    }

    // 2) Fused Q/K/V projections + RoPE + split (HMMA, 4-stage pipeline)
    gemm_hmma<true><<<dim3(DIM / 128, S_LEN / 128, 3), 256, GEMM_SMEM>>>(
        xhi, xlo, whi, wlo, nullptr,
        qhi, qlo, khi, klo, vhi, vlo);

    // 3) Sliding-window attention (HMMA split-bf16, fused output split)
    attn_hmma<<<dim3(S_LEN / 128, NH), 256, ATN_SMEM>>>(
        qhi, qlo, khi, klo, vhi, vlo, ohi, olo);

    // 4) Output projection (HMMA, 4-stage pipeline, fp32 out)
    gemm_hmma<false><<<dim3(DIM / 128, S_LEN / 128, 1), 256, GEMM_SMEM>>>(
        ohi, olo, whi + 3 * DIM * DIM, wlo + 3 * DIM * DIM, out,
        nullptr, nullptr, nullptr, nullptr, nullptr, nullptr);
}

// round 14
// speedup vs baseline: 1.1517x; 1.1517x over previous
#include <cuda_runtime.h>
#include <cuda_bf16.h>
#include <math.h>
#include <cstdint>

#define S_LEN 8192
#define DIM   1024
#define NH    16
#define HD    64
#define WIN   512

// ---------------- scratch (allocation-free rule: device globals) ----------
__device__ __align__(256) __nv_bfloat16 g_xhi[S_LEN * DIM];
__device__ __align__(256) __nv_bfloat16 g_xlo[S_LEN * DIM];
__device__ __align__(256) __nv_bfloat16 g_whi[4 * DIM * DIM];
__device__ __align__(256) __nv_bfloat16 g_wlo[4 * DIM * DIM];
__device__ __align__(256) __nv_bfloat16 g_qhi[S_LEN * DIM];
__device__ __align__(256) __nv_bfloat16 g_qlo[S_LEN * DIM];
__device__ __align__(256) __nv_bfloat16 g_khi[S_LEN * DIM];
__device__ __align__(256) __nv_bfloat16 g_klo[S_LEN * DIM];
__device__ __align__(256) __nv_bfloat16 g_vhi[S_LEN * DIM];
__device__ __align__(256) __nv_bfloat16 g_vlo[S_LEN * DIM];
__device__ __align__(256) __nv_bfloat16 g_ohi[S_LEN * DIM];
__device__ __align__(256) __nv_bfloat16 g_olo[S_LEN * DIM];

// ---------------- fused fp32 -> bf16 hi/lo split (x + 4 weights) -----------
#define XN4 (S_LEN * DIM / 4)
#define WN4 (DIM * DIM / 4)
__global__ void split_all_kernel(const float* __restrict__ x,
                                 const float* __restrict__ Wq,
                                 const float* __restrict__ Wk,
                                 const float* __restrict__ Wv,
                                 const float* __restrict__ Wo,
                                 __nv_bfloat16* __restrict__ xhi,
                                 __nv_bfloat16* __restrict__ xlo,
                                 __nv_bfloat16* __restrict__ whi,
                                 __nv_bfloat16* __restrict__ wlo)
{
    int i = blockIdx.x * blockDim.x + threadIdx.x;
    const float* src;
    __nv_bfloat16 *hi, *lo;
    int idx;
    if (i < XN4) {
        src = x; hi = xhi; lo = xlo; idx = i;
    } else {
        int j = i - XN4;
        if (j >= 4 * WN4) return;
        int w = j / WN4;
        idx = j - w * WN4;
        src = (w == 0) ? Wq : (w == 1) ? Wk : (w == 2) ? Wv : Wo;
        hi = whi + (size_t)w * DIM * DIM;
        lo = wlo + (size_t)w * DIM * DIM;
    }
    float4 v = ((const float4*)src)[idx];
    __nv_bfloat16 h0 = __float2bfloat16(v.x);
    __nv_bfloat16 h1 = __float2bfloat16(v.y);
    __nv_bfloat16 h2 = __float2bfloat16(v.z);
    __nv_bfloat16 h3 = __float2bfloat16(v.w);
    __nv_bfloat16 l0 = __float2bfloat16(v.x - __bfloat162float(h0));
    __nv_bfloat16 l1 = __float2bfloat16(v.y - __bfloat162float(h1));
    __nv_bfloat16 l2 = __float2bfloat16(v.z - __bfloat162float(h2));
    __nv_bfloat16 l3 = __float2bfloat16(v.w - __bfloat162float(h3));
    uint2 uh, ul;
    uh.x = (uint32_t)__bfloat16_as_ushort(h0) | ((uint32_t)__bfloat16_as_ushort(h1) << 16);
    uh.y = (uint32_t)__bfloat16_as_ushort(h2) | ((uint32_t)__bfloat16_as_ushort(h3) << 16);
    ul.x = (uint32_t)__bfloat16_as_ushort(l0) | ((uint32_t)__bfloat16_as_ushort(l1) << 16);
    ul.y = (uint32_t)__bfloat16_as_ushort(l2) | ((uint32_t)__bfloat16_as_ushort(l3) << 16);
    ((uint2*)hi)[idx] = uh;
    ((uint2*)lo)[idx] = ul;
}

// ---------------- HMMA helpers --------------------------------------------
__device__ __forceinline__ uint32_t smem_u32(const void* p) {
    uint32_t a;
    asm("{ .reg .u64 t; cvta.to.shared.u64 t, %1; cvt.u32.u64 %0, t; }"
        : "=r"(a) : "l"(p));
    return a;
}
__device__ __forceinline__ void ldsm_x4(uint32_t* r, uint32_t saddr) {
    asm volatile("ldmatrix.sync.aligned.m8n8.x4.shared.b16 {%0,%1,%2,%3}, [%4];"
                 : "=r"(r[0]), "=r"(r[1]), "=r"(r[2]), "=r"(r[3]) : "r"(saddr));
}
__device__ __forceinline__ void ldsm_x4_trans(uint32_t* r, uint32_t saddr) {
    asm volatile("ldmatrix.sync.aligned.m8n8.x4.trans.shared.b16 {%0,%1,%2,%3}, [%4];"
                 : "=r"(r[0]), "=r"(r[1]), "=r"(r[2]), "=r"(r[3]) : "r"(saddr));
}
__device__ __forceinline__ void mma_bf16(float* c, const uint32_t* a,
                                         uint32_t b0, uint32_t b1) {
    asm volatile(
        "mma.sync.aligned.m16n8k16.row.col.f32.bf16.bf16.f32 "
        "{%0,%1,%2,%3}, {%4,%5,%6,%7}, {%8,%9}, {%0,%1,%2,%3};"
        : "+f"(c[0]), "+f"(c[1]), "+f"(c[2]), "+f"(c[3])
        : "r"(a[0]), "r"(a[1]), "r"(a[2]), "r"(a[3]), "r"(b0), "r"(b1));
}
#define CP_ASYNC16(saddr, gptr) \
    asm volatile("cp.async.ca.shared.global [%0], [%1], 16;" \
                 :: "r"(saddr), "l"(gptr))
#define CP_COMMIT()  asm volatile("cp.async.commit_group;" ::: "memory")
#define CP_WAIT(n)   asm volatile("cp.async.wait_group %0;" :: "n"(n) : "memory")

// pack two floats -> bf16x2 word
__device__ __forceinline__ uint32_t pack_bf2(float x, float y) {
    __nv_bfloat16 bx = __float2bfloat16(x), by = __float2bfloat16(y);
    return (uint32_t)__bfloat16_as_ushort(bx) |
           ((uint32_t)__bfloat16_as_ushort(by) << 16);
}
__device__ __forceinline__ void split_pair(float x, float y,
                                           uint32_t& hw, uint32_t& lw) {
    __nv_bfloat16 hx = __float2bfloat16(x), hy = __float2bfloat16(y);
    hw = (uint32_t)__bfloat16_as_ushort(hx) |
         ((uint32_t)__bfloat16_as_ushort(hy) << 16);
    lw = pack_bf2(x - __bfloat162float(hx), y - __bfloat162float(hy));
}

// ---------------- HMMA split-fp32 GEMM NT, 2-stage, 2 CTAs/SM --------------
// FS=true: epilogue applies RoPE (z<2) and writes bf16 hi/lo (fused split).
// FS=false: epilogue writes fp32 C0.
#define SKB   40
#define TILEB (128 * SKB * 2)
#define STAGEB (4 * TILEB)               // 40960 B
#define GEMM_SMEM (2 * STAGEB)           // 81920 B -> 2 CTAs/SM
#define NCHUNK (DIM / 32)

template <bool FS>
__global__ __launch_bounds__(256, 2)
void gemm_hmma(const __nv_bfloat16* __restrict__ Ahi,
               const __nv_bfloat16* __restrict__ Alo,
               const __nv_bfloat16* __restrict__ Bhi_all,
               const __nv_bfloat16* __restrict__ Blo_all,
               float* __restrict__ C0,
               __nv_bfloat16* __restrict__ H0, __nv_bfloat16* __restrict__ L0,
               __nv_bfloat16* __restrict__ H1, __nv_bfloat16* __restrict__ L1,
               __nv_bfloat16* __restrict__ H2, __nv_bfloat16* __restrict__ L2)
{
    extern __shared__ char smem[];
    const uint32_t sb = smem_u32(smem);
    const int t    = threadIdx.x;
    const int wid  = t >> 5;
    const int lane = t & 31;
    const int bm = blockIdx.y * 128;
    const int bn = blockIdx.x * 128;
    const int z  = blockIdx.z;
    const __nv_bfloat16* bhi = Bhi_all + (size_t)z * DIM * DIM;
    const __nv_bfloat16* blo = Blo_all + (size_t)z * DIM * DIM;

    const int wm = (wid >> 2) * 64;
    const int wn = (wid & 3) * 32;

    float acc[4][4][4];
#pragma unroll
    for (int i = 0; i < 4; i++)
#pragma unroll
        for (int j = 0; j < 4; j++)
#pragma unroll
            for (int r = 0; r < 4; r++) acc[i][j][r] = 0.0f;

    auto issue_chunk = [&](int kc, int stage) {
        const uint32_t sbase = sb + stage * STAGEB;
#pragma unroll
        for (int i = 0; i < 8; i++) {
            int id   = t + 256 * i;
            int tile = id >> 9;
            int w    = id & 511;
            int row  = w >> 2;
            int cg   = (w & 3) * 8;
            uint32_t so = sbase + tile * TILEB + (uint32_t)(row * SKB + cg) * 2;
            const __nv_bfloat16* gp;
            if (tile == 0)      gp = Ahi + (size_t)(bm + row) * DIM + kc + cg;
            else if (tile == 1) gp = Alo + (size_t)(bm + row) * DIM + kc + cg;
            else if (tile == 2) gp = bhi + (size_t)(bn + row) * DIM + kc + cg;
            else                gp = blo + (size_t)(bn + row) * DIM + kc + cg;
            CP_ASYNC16(so, gp);
        }
        CP_COMMIT();
    };

    issue_chunk(0, 0);

    const int lrow = lane & 7;
    const int seg  = lane >> 3;

    for (int c = 0; c < NCHUNK; c++) {
        CP_WAIT(0);
        __syncthreads();
        if (c + 1 < NCHUNK) issue_chunk((c + 1) * 32, (c + 1) & 1);

        const uint32_t stg = sb + (c & 1) * STAGEB;
#pragma unroll
        for (int ks = 0; ks < 32; ks += 16) {
            uint32_t bh[2][4], bl[2][4];
#pragma unroll
            for (int p = 0; p < 2; p++) {
                int br = wn + p * 16 + (seg >> 1) * 8 + lrow;
                int bc = ks + (seg & 1) * 8;
                uint32_t off = (uint32_t)(br * SKB + bc) * 2;
                ldsm_x4(bh[p], stg + 2 * TILEB + off);
                ldsm_x4(bl[p], stg + 3 * TILEB + off);
            }
#pragma unroll
            for (int mt = 0; mt < 4; mt++) {
                int ar = wm + mt * 16 + (seg & 1) * 8 + lrow;
                int ac = ks + (seg >> 1) * 8;
                uint32_t off = (uint32_t)(ar * SKB + ac) * 2;
                uint32_t ah[4], al[4];
                ldsm_x4(ah, stg + 0 * TILEB + off);
                ldsm_x4(al, stg + 1 * TILEB + off);
#pragma unroll
                for (int nt = 0; nt < 4; nt++) {
                    int p = nt >> 1, q = (nt & 1) * 2;
                    mma_bf16(acc[mt][nt], ah, bh[p][q], bh[p][q + 1]);
                    mma_bf16(acc[mt][nt], ah, bl[p][q], bl[p][q + 1]);
                    mma_bf16(acc[mt][nt], al, bh[p][q], bh[p][q + 1]);
                }
            }
        }
        __syncthreads();
    }

    const int trow = lane >> 2;
    const int tcol = (lane & 3) * 2;

    if (!FS) {
#pragma unroll
        for (int mt = 0; mt < 4; mt++) {
#pragma unroll
            for (int nt = 0; nt < 4; nt++) {
                size_t r0 = (size_t)(bm + wm + mt * 16 + trow);
                size_t cc = (size_t)(bn + wn + nt * 8 + tcol);
                *(float2*)(C0 + r0 * DIM + cc) =
                    make_float2(acc[mt][nt][0], acc[mt][nt][1]);
                *(float2*)(C0 + (r0 + 8) * DIM + cc) =
                    make_float2(acc[mt][nt][2], acc[mt][nt][3]);
            }
        }
    } else {
        __nv_bfloat16* Hp = (z == 0) ? H0 : (z == 1 ? H1 : H2);
        __nv_bfloat16* Lp = (z == 0) ? L0 : (z == 1 ? L1 : L2);
        const bool rope = (z != 2);
#pragma unroll
        for (int nt = 0; nt < 4; nt++) {
            int cc = bn + wn + nt * 8 + tcol;
            float invf = 0.0f;
            if (rope) {
                int j = (cc & 63) >> 1;
                invf = 1.0f / powf(10000.0f, (float)(2 * j) * (1.0f / 64.0f));
            }
#pragma unroll
            for (int mt = 0; mt < 4; mt++) {
                int r0 = bm + wm + mt * 16 + trow;
                float a0 = acc[mt][nt][0], a1 = acc[mt][nt][1];
                float a2 = acc[mt][nt][2], a3 = acc[mt][nt][3];
                if (rope) {
                    float s0, c0, s1, c1;
                    sincosf((float)r0 * invf, &s0, &c0);
                    sincosf((float)(r0 + 8) * invf, &s1, &c1);
                    float n0 = a0 * c0 - a1 * s0;
                    float n1 = a0 * s0 + a1 * c0;
                    float n2 = a2 * c1 - a3 * s1;
                    float n3 = a2 * s1 + a3 * c1;
                    a0 = n0; a1 = n1; a2 = n2; a3 = n3;
                }
                uint32_t hw0, lw0, hw1, lw1;
                split_pair(a0, a1, hw0, lw0);
                split_pair(a2, a3, hw1, lw1);
                size_t base0 = (size_t)r0 * DIM + cc;
                size_t base1 = (size_t)(r0 + 8) * DIM + cc;
                *(uint32_t*)(Hp + base0) = hw0;
                *(uint32_t*)(Lp + base0) = lw0;
                *(uint32_t*)(Hp + base1) = hw1;
                *(uint32_t*)(Lp + base1) = lw1;
            }
        }
    }
}

// ---------------- HMMA split-bf16 sliding-window flash attention -----------
#define SKD 72
#define ATN_Q_HI 0
#define ATN_Q_LO 18432
#define ATN_K_HI 36864
#define ATN_K_LO 55296
#define ATN_V_HI 73728
#define ATN_V_LO 92160
#define ATN_SMEM 110592

__global__ __launch_bounds__(256, 1) void attn_hmma(
    const __nv_bfloat16* __restrict__ qhi, const __nv_bfloat16* __restrict__ qlo,
    const __nv_bfloat16* __restrict__ khi, const __nv_bfloat16* __restrict__ klo,
    const __nv_bfloat16* __restrict__ vhi, const __nv_bfloat16* __restrict__ vlo,
    __nv_bfloat16* __restrict__ ohi, __nv_bfloat16* __restrict__ olo)
{
    extern __shared__ char sms[];
    const uint32_t sb = smem_u32(sms);
    const int t = threadIdx.x;
    const int lane = t & 31;
    const int wid  = t >> 5;
    const int h  = blockIdx.y;
    const int qs = blockIdx.x * 128;
    const int lrow = lane & 7;
    const int seg  = lane >> 3;

#pragma unroll
    for (int i = 0; i < 4; i++) {
        int f = i * 256 + t;
        int r = f >> 3, cg = (f & 7) * 8;
        uint32_t so = (uint32_t)(r * SKD + cg) * 2;
        size_t g = (size_t)(qs + r) * DIM + h * HD + cg;
        *(uint4*)(sms + ATN_Q_HI + so) = *(const uint4*)(qhi + g);
        *(uint4*)(sms + ATN_Q_LO + so) = *(const uint4*)(qlo + g);
    }
    __syncthreads();

    uint32_t aQh[4][4], aQl[4][4];
    {
        int ar = wid * 16 + (seg & 1) * 8 + lrow;
#pragma unroll
        for (int ks = 0; ks < 4; ks++) {
            int ac = ks * 16 + (seg >> 1) * 8;
            uint32_t off = (uint32_t)(ar * SKD + ac) * 2;
            ldsm_x4(aQh[ks], sb + ATN_Q_HI + off);
            ldsm_x4(aQl[ks], sb + ATN_Q_LO + off);
        }
    }

    float m0 = -1e30f, m1 = -1e30f, l0 = 0.0f, l1 = 0.0f;
    float oa[8][4];
#pragma unroll
    for (int i = 0; i < 8; i++)
#pragma unroll
        for (int j = 0; j < 4; j++) oa[i][j] = 0.0f;

    const int r0 = wid * 16 + (lane >> 2);
    const int qg0 = qs + r0;
    const int qg1 = qg0 + 8;

    int kt0 = qs - WIN;
    if (kt0 < 0) kt0 = 0;

    for (int kt = kt0; kt <= qs; kt += 128) {
        __syncthreads();
#pragma unroll
        for (int i = 0; i < 4; i++) {
            int f = i * 256 + t;
            int r = f >> 3, cg = (f & 7) * 8;
            uint32_t so = (uint32_t)(r * SKD + cg) * 2;
            size_t g = (size_t)(kt + r) * DIM + h * HD + cg;
            *(uint4*)(sms + ATN_K_HI + so) = *(const uint4*)(khi + g);
            *(uint4*)(sms + ATN_K_LO + so) = *(const uint4*)(klo + g);
            *(uint4*)(sms + ATN_V_HI + so) = *(const uint4*)(vhi + g);
            *(uint4*)(sms + ATN_V_LO + so) = *(const uint4*)(vlo + g);
        }
        __syncthreads();

        float sc[16][4];
#pragma unroll
        for (int i = 0; i < 16; i++)
#pragma unroll
            for (int j = 0; j < 4; j++) sc[i][j] = 0.0f;

#pragma unroll
        for (int ks = 0; ks < 4; ks++) {
#pragma unroll
            for (int bp = 0; bp < 8; bp++) {
                uint32_t bh[4], bl[4];
                int br = bp * 16 + (seg >> 1) * 8 + lrow;
                int bc = ks * 16 + (seg & 1) * 8;
                uint32_t off = (uint32_t)(br * SKD + bc) * 2;
                ldsm_x4(bh, sb + ATN_K_HI + off);
                ldsm_x4(bl, sb + ATN_K_LO + off);
                mma_bf16(sc[2 * bp],     aQh[ks], bh[0], bh[1]);
                mma_bf16(sc[2 * bp],     aQh[ks], bl[0], bl[1]);
                mma_bf16(sc[2 * bp],     aQl[ks], bh[0], bh[1]);
                mma_bf16(sc[2 * bp + 1], aQh[ks], bh[2], bh[3]);
                mma_bf16(sc[2 * bp + 1], aQh[ks], bl[2], bl[3]);
                mma_bf16(sc[2 * bp + 1], aQl[ks], bh[2], bh[3]);
            }
        }

        float nm0 = m0, nm1 = m1;
#pragma unroll
        for (int nt = 0; nt < 16; nt++) {
            int kg = kt + nt * 8 + (lane & 3) * 2;
            sc[nt][0] = (kg     <= qg0 && kg     > qg0 - WIN) ? sc[nt][0] * 0.125f : -1e30f;
            sc[nt][1] = (kg + 1 <= qg0 && kg + 1 > qg0 - WIN) ? sc[nt][1] * 0.125f : -1e30f;
            sc[nt][2] = (kg     <= qg1 && kg     > qg1 - WIN) ? sc[nt][2] * 0.125f : -1e30f;
            sc[nt][3] = (kg + 1 <= qg1 && kg + 1 > qg1 - WIN) ? sc[nt][3] * 0.125f : -1e30f;
            nm0 = fmaxf(nm0, fmaxf(sc[nt][0], sc[nt][1]));
            nm1 = fmaxf(nm1, fmaxf(sc[nt][2], sc[nt][3]));
        }
        nm0 = fmaxf(nm0, __shfl_xor_sync(0xffffffffu, nm0, 1));
        nm0 = fmaxf(nm0, __shfl_xor_sync(0xffffffffu, nm0, 2));
        nm1 = fmaxf(nm1, __shfl_xor_sync(0xffffffffu, nm1, 1));
        nm1 = fmaxf(nm1, __shfl_xor_sync(0xffffffffu, nm1, 2));

        float al0 = __expf(m0 - nm0);
        float al1 = __expf(m1 - nm1);
        m0 = nm0; m1 = nm1;

        float rs0 = 0.0f, rs1 = 0.0f;
#pragma unroll
        for (int nt = 0; nt < 16; nt++) {
            float p0 = (sc[nt][0] > -1e29f) ? __expf(sc[nt][0] - m0) : 0.0f;
            float p1 = (sc[nt][1] > -1e29f) ? __expf(sc[nt][1] - m0) : 0.0f;
            float p2 = (sc[nt][2] > -1e29f) ? __expf(sc[nt][2] - m1) : 0.0f;
            float p3 = (sc[nt][3] > -1e29f) ? __expf(sc[nt][3] - m1) : 0.0f;
            sc[nt][0] = p0; sc[nt][1] = p1; sc[nt][2] = p2; sc[nt][3] = p3;
            rs0 += p0 + p1;
            rs1 += p2 + p3;
        }
        rs0 += __shfl_xor_sync(0xffffffffu, rs0, 1);
        rs0 += __shfl_xor_sync(0xffffffffu, rs0, 2);
        rs1 += __shfl_xor_sync(0xffffffffu, rs1, 1);
        rs1 += __shfl_xor_sync(0xffffffffu, rs1, 2);
        l0 = l0 * al0 + rs0;
        l1 = l1 * al1 + rs1;

#pragma unroll
        for (int i = 0; i < 8; i++) {
            oa[i][0] *= al0; oa[i][1] *= al0;
            oa[i][2] *= al1; oa[i][3] *= al1;
        }

#pragma unroll
        for (int j = 0; j < 8; j++) {
            float p00 = sc[2 * j][0],     p01 = sc[2 * j][1];
            float p02 = sc[2 * j][2],     p03 = sc[2 * j][3];
            float p10 = sc[2 * j + 1][0], p11 = sc[2 * j + 1][1];
            float p12 = sc[2 * j + 1][2], p13 = sc[2 * j + 1][3];
            uint32_t pah[4], pal[4];
            split_pair(p00, p01, pah[0], pal[0]);
            split_pair(p02, p03, pah[1], pal[1]);
            split_pair(p10, p11, pah[2], pal[2]);
            split_pair(p12, p13, pah[3], pal[3]);
#pragma unroll
            for (int dp = 0; dp < 4; dp++) {
                uint32_t bh[4], bl[4];
                int kk = j * 16 + (seg & 1) * 8 + lrow;
                int nn = dp * 16 + (seg >> 1) * 8;
                uint32_t off = (uint32_t)(kk * SKD + nn) * 2;
                ldsm_x4_trans(bh, sb + ATN_V_HI + off);
                ldsm_x4_trans(bl, sb + ATN_V_LO + off);
                mma_bf16(oa[dp * 2],     pah, bh[0], bh[1]);
                mma_bf16(oa[dp * 2],     pah, bl[0], bl[1]);
                mma_bf16(oa[dp * 2],     pal, bh[0], bh[1]);
                mma_bf16(oa[dp * 2 + 1], pah, bh[2], bh[3]);
                mma_bf16(oa[dp * 2 + 1], pah, bl[2], bl[3]);
                mma_bf16(oa[dp * 2 + 1], pal, bh[2], bh[3]);
            }
        }
    }

    float inv0 = 1.0f / l0;
    float inv1 = 1.0f / l1;
    const int tcol = (lane & 3) * 2;
#pragma unroll
    for (int dt = 0; dt < 8; dt++) {
        size_t c = (size_t)(h * HD + dt * 8 + tcol);
        uint32_t hw0, lw0, hw1, lw1;
        split_pair(oa[dt][0] * inv0, oa[dt][1] * inv0, hw0, lw0);
        split_pair(oa[dt][2] * inv1, oa[dt][3] * inv1, hw1, lw1);
        size_t b0 = (size_t)qg0 * DIM + c;
        size_t b1 = (size_t)qg1 * DIM + c;
        *(uint32_t*)(ohi + b0) = hw0;
        *(uint32_t*)(olo + b0) = lw0;
        *(uint32_t*)(ohi + b1) = hw1;
        *(uint32_t*)(olo + b1) = lw1;
    }
}

// ---------------------------------------------------------------------------
extern "C" void kernel_launch(void* const* d_in, const int* in_sizes, int n_in,
                              void* d_out, int out_size)
{
    const float* x  = (const float*)d_in[0];
    const float* Wq = (const float*)d_in[1];
    const float* Wk = (const float*)d_in[2];
    const float* Wv = (const float*)d_in[3];
    const float* Wo = (const float*)d_in[4];
    float* out = (float*)d_out;

    __nv_bfloat16 *xhi, *xlo, *whi, *wlo;
    __nv_bfloat16 *qhi, *qlo, *khi, *klo, *vhi, *vlo, *ohi, *olo;
    cudaGetSymbolAddress((void**)&xhi, g_xhi);
    cudaGetSymbolAddress((void**)&xlo, g_xlo);
    cudaGetSymbolAddress((void**)&whi, g_whi);
    cudaGetSymbolAddress((void**)&wlo, g_wlo);
    cudaGetSymbolAddress((void**)&qhi, g_qhi);
    cudaGetSymbolAddress((void**)&qlo, g_qlo);
    cudaGetSymbolAddress((void**)&khi, g_khi);
    cudaGetSymbolAddress((void**)&klo, g_klo);
    cudaGetSymbolAddress((void**)&vhi, g_vhi);
    cudaGetSymbolAddress((void**)&vlo, g_vlo);
    cudaGetSymbolAddress((void**)&ohi, g_ohi);
    cudaGetSymbolAddress((void**)&olo, g_olo);

    cudaFuncSetAttribute(gemm_hmma<true>,
                         cudaFuncAttributeMaxDynamicSharedMemorySize, GEMM_SMEM);
    cudaFuncSetAttribute(gemm_hmma<false>,
                         cudaFuncAttributeMaxDynamicSharedMemorySize, GEMM_SMEM);
    cudaFuncSetAttribute(attn_hmma,
                         cudaFuncAttributeMaxDynamicSharedMemorySize, ATN_SMEM);

    // 1) Fused split of x + all 4 weights into bf16 hi/lo (single launch)
    {
        int total = XN4 + 4 * WN4;
        split_all_kernel<<<(total + 255) / 256, 256>>>(
            x, Wq, Wk, Wv, Wo, xhi, xlo, whi, wlo);
    }

    // 2) Fused Q/K/V projections + RoPE + split (HMMA, 2-stage, 2 CTAs/SM)
    gemm_hmma<true><<<dim3(DIM / 128, S_LEN / 128, 3), 256, GEMM_SMEM>>>(
        xhi, xlo, whi, wlo, nullptr,
        qhi, qlo, khi, klo, vhi, vlo);

    // 3) Sliding-window attention (HMMA split-bf16, fused output split)
    attn_hmma<<<dim3(S_LEN / 128, NH), 256, ATN_SMEM>>>(
        qhi, qlo, khi, klo, vhi, vlo, ohi, olo);

    // 4) Output projection (HMMA, 2-stage, 2 CTAs/SM, fp32 out)
    gemm_hmma<false><<<dim3(DIM / 128, S_LEN / 128, 1), 256, GEMM_SMEM>>>(
        ohi, olo, whi + 3 * DIM * DIM, wlo + 3 * DIM * DIM, out,
        nullptr, nullptr, nullptr, nullptr, nullptr, nullptr);
}

// round 16
// speedup vs baseline: 1.3947x; 1.2110x over previous
#include <cuda_runtime.h>
#include <cuda_bf16.h>
#include <cuda_fp16.h>
#include <math.h>
#include <cstdint>

#define S_LEN 8192
#define DIM   1024
#define NH    16
#define HD    64
#define WIN   512

// ---------------- scratch (allocation-free rule: device globals) ----------
__device__ __align__(256) __half g_xhi[S_LEN * DIM];
__device__ __align__(256) __half g_xlo[S_LEN * DIM];
__device__ __align__(256) __half g_w[4 * DIM * DIM];      // fp16-rounded weights
__device__ __align__(256) __nv_bfloat16 g_qhi[S_LEN * DIM];
__device__ __align__(256) __nv_bfloat16 g_qlo[S_LEN * DIM];
__device__ __align__(256) __nv_bfloat16 g_khi[S_LEN * DIM];
__device__ __align__(256) __nv_bfloat16 g_klo[S_LEN * DIM];
__device__ __align__(256) __nv_bfloat16 g_vhi[S_LEN * DIM];
__device__ __align__(256) __nv_bfloat16 g_vlo[S_LEN * DIM];
__device__ __align__(256) __half g_ohi[S_LEN * DIM];
__device__ __align__(256) __half g_olo[S_LEN * DIM];

// ---------------- fused split kernel: x -> fp16 hi/lo, W -> fp16 ----------
#define XN4 (S_LEN * DIM / 4)
#define WN4 (DIM * DIM / 4)
__global__ void split_all_kernel(const float* __restrict__ x,
                                 const float* __restrict__ Wq,
                                 const float* __restrict__ Wk,
                                 const float* __restrict__ Wv,
                                 const float* __restrict__ Wo,
                                 __half* __restrict__ xhi,
                                 __half* __restrict__ xlo,
                                 __half* __restrict__ w)
{
    int i = blockIdx.x * blockDim.x + threadIdx.x;
    if (i < XN4) {
        float4 v = ((const float4*)x)[i];
        __half h0 = __float2half_rn(v.x);
        __half h1 = __float2half_rn(v.y);
        __half h2 = __float2half_rn(v.z);
        __half h3 = __float2half_rn(v.w);
        __half l0 = __float2half_rn(v.x - __half2float(h0));
        __half l1 = __float2half_rn(v.y - __half2float(h1));
        __half l2 = __float2half_rn(v.z - __half2float(h2));
        __half l3 = __float2half_rn(v.w - __half2float(h3));
        uint2 uh, ul;
        uh.x = (uint32_t)__half_as_ushort(h0) | ((uint32_t)__half_as_ushort(h1) << 16);
        uh.y = (uint32_t)__half_as_ushort(h2) | ((uint32_t)__half_as_ushort(h3) << 16);
        ul.x = (uint32_t)__half_as_ushort(l0) | ((uint32_t)__half_as_ushort(l1) << 16);
        ul.y = (uint32_t)__half_as_ushort(l2) | ((uint32_t)__half_as_ushort(l3) << 16);
        ((uint2*)xhi)[i] = uh;
        ((uint2*)xlo)[i] = ul;
    } else {
        int j = i - XN4;
        if (j >= 4 * WN4) return;
        int wsel = j / WN4;
        int idx = j - wsel * WN4;
        const float* src = (wsel == 0) ? Wq : (wsel == 1) ? Wk : (wsel == 2) ? Wv : Wo;
        float4 v = ((const float4*)src)[idx];
        __half h0 = __float2half_rn(v.x);
        __half h1 = __float2half_rn(v.y);
        __half h2 = __float2half_rn(v.z);
        __half h3 = __float2half_rn(v.w);
        uint2 uh;
        uh.x = (uint32_t)__half_as_ushort(h0) | ((uint32_t)__half_as_ushort(h1) << 16);
        uh.y = (uint32_t)__half_as_ushort(h2) | ((uint32_t)__half_as_ushort(h3) << 16);
        ((uint2*)(w + (size_t)wsel * DIM * DIM))[idx] = uh;
    }
}

// ---------------- MMA helpers ----------------------------------------------
__device__ __forceinline__ uint32_t smem_u32(const void* p) {
    uint32_t a;
    asm("{ .reg .u64 t; cvta.to.shared.u64 t, %1; cvt.u32.u64 %0, t; }"
        : "=r"(a) : "l"(p));
    return a;
}
__device__ __forceinline__ void ldsm_x4(uint32_t* r, uint32_t saddr) {
    asm volatile("ldmatrix.sync.aligned.m8n8.x4.shared.b16 {%0,%1,%2,%3}, [%4];"
                 : "=r"(r[0]), "=r"(r[1]), "=r"(r[2]), "=r"(r[3]) : "r"(saddr));
}
__device__ __forceinline__ void ldsm_x4_trans(uint32_t* r, uint32_t saddr) {
    asm volatile("ldmatrix.sync.aligned.m8n8.x4.trans.shared.b16 {%0,%1,%2,%3}, [%4];"
                 : "=r"(r[0]), "=r"(r[1]), "=r"(r[2]), "=r"(r[3]) : "r"(saddr));
}
__device__ __forceinline__ void mma_bf16(float* c, const uint32_t* a,
                                         uint32_t b0, uint32_t b1) {
    asm volatile(
        "mma.sync.aligned.m16n8k16.row.col.f32.bf16.bf16.f32 "
        "{%0,%1,%2,%3}, {%4,%5,%6,%7}, {%8,%9}, {%0,%1,%2,%3};"
        : "+f"(c[0]), "+f"(c[1]), "+f"(c[2]), "+f"(c[3])
        : "r"(a[0]), "r"(a[1]), "r"(a[2]), "r"(a[3]), "r"(b0), "r"(b1));
}
__device__ __forceinline__ void mma_f16(float* c, const uint32_t* a,
                                        uint32_t b0, uint32_t b1) {
    asm volatile(
        "mma.sync.aligned.m16n8k16.row.col.f32.f16.f16.f32 "
        "{%0,%1,%2,%3}, {%4,%5,%6,%7}, {%8,%9}, {%0,%1,%2,%3};"
        : "+f"(c[0]), "+f"(c[1]), "+f"(c[2]), "+f"(c[3])
        : "r"(a[0]), "r"(a[1]), "r"(a[2]), "r"(a[3]), "r"(b0), "r"(b1));
}
#define CP_ASYNC16(saddr, gptr) \
    asm volatile("cp.async.ca.shared.global [%0], [%1], 16;" \
                 :: "r"(saddr), "l"(gptr))
#define CP_COMMIT()  asm volatile("cp.async.commit_group;" ::: "memory")
#define CP_WAIT(n)   asm volatile("cp.async.wait_group %0;" :: "n"(n) : "memory")

// bf16 split pair (attention q/k/v path)
__device__ __forceinline__ void split_pair_bf(float x, float y,
                                              uint32_t& hw, uint32_t& lw) {
    __nv_bfloat16 hx = __float2bfloat16(x), hy = __float2bfloat16(y);
    hw = (uint32_t)__bfloat16_as_ushort(hx) |
         ((uint32_t)__bfloat16_as_ushort(hy) << 16);
    __nv_bfloat16 lx = __float2bfloat16(x - __bfloat162float(hx));
    __nv_bfloat16 ly = __float2bfloat16(y - __bfloat162float(hy));
    lw = (uint32_t)__bfloat16_as_ushort(lx) |
         ((uint32_t)__bfloat16_as_ushort(ly) << 16);
}
// fp16 split pair (attention output -> final GEMM)
__device__ __forceinline__ void split_pair_h(float x, float y,
                                             uint32_t& hw, uint32_t& lw) {
    __half hx = __float2half_rn(x), hy = __float2half_rn(y);
    hw = (uint32_t)__half_as_ushort(hx) |
         ((uint32_t)__half_as_ushort(hy) << 16);
    __half lx = __float2half_rn(x - __half2float(hx));
    __half ly = __float2half_rn(y - __half2float(hy));
    lw = (uint32_t)__half_as_ushort(lx) |
         ((uint32_t)__half_as_ushort(ly) << 16);
}

// ---------------- fp16 2-term GEMM NT, 2-stage, 2 CTAs/SM ------------------
// D = Ahi*B + Alo*B  (A = activation split to fp16 hi/lo; B = fp16 weights).
// FS=true: epilogue applies RoPE (z<2) and writes bf16 hi/lo for attention.
// FS=false: epilogue writes fp32 C0.
#define SKB   40
#define TILEB (128 * SKB * 2)            // 10240 B
#define STAGEB (3 * TILEB)               // 30720 B (Ahi, Alo, B)
#define GEMM_SMEM (2 * STAGEB)           // 61440 B -> 2 CTAs/SM
#define NCHUNK (DIM / 32)

template <bool FS>
__global__ __launch_bounds__(256, 2)
void gemm_hmma(const __half* __restrict__ Ahi,
               const __half* __restrict__ Alo,
               const __half* __restrict__ B_all,
               float* __restrict__ C0,
               __nv_bfloat16* __restrict__ H0, __nv_bfloat16* __restrict__ L0,
               __nv_bfloat16* __restrict__ H1, __nv_bfloat16* __restrict__ L1,
               __nv_bfloat16* __restrict__ H2, __nv_bfloat16* __restrict__ L2)
{
    extern __shared__ char smem[];
    const uint32_t sb = smem_u32(smem);
    const int t    = threadIdx.x;
    const int wid  = t >> 5;
    const int lane = t & 31;
    const int bm = blockIdx.y * 128;
    const int bn = blockIdx.x * 128;
    const int z  = blockIdx.z;
    const __half* Bw = B_all + (size_t)z * DIM * DIM;

    const int wm = (wid >> 2) * 64;
    const int wn = (wid & 3) * 32;

    float acc[4][4][4];
#pragma unroll
    for (int i = 0; i < 4; i++)
#pragma unroll
        for (int j = 0; j < 4; j++)
#pragma unroll
            for (int r = 0; r < 4; r++) acc[i][j][r] = 0.0f;

    auto issue_chunk = [&](int kc, int stage) {
        const uint32_t sbase = sb + stage * STAGEB;
#pragma unroll
        for (int i = 0; i < 6; i++) {
            int id   = t + 256 * i;          // 0..1535
            int tile = id >> 9;              // 0=Ahi 1=Alo 2=B
            int w    = id & 511;
            int row  = w >> 2;
            int cg   = (w & 3) * 8;
            uint32_t so = sbase + tile * TILEB + (uint32_t)(row * SKB + cg) * 2;
            const __half* gp;
            if (tile == 0)      gp = Ahi + (size_t)(bm + row) * DIM + kc + cg;
            else if (tile == 1) gp = Alo + (size_t)(bm + row) * DIM + kc + cg;
            else                gp = Bw  + (size_t)(bn + row) * DIM + kc + cg;
            CP_ASYNC16(so, gp);
        }
        CP_COMMIT();
    };

    issue_chunk(0, 0);

    const int lrow = lane & 7;
    const int seg  = lane >> 3;

    for (int c = 0; c < NCHUNK; c++) {
        CP_WAIT(0);
        __syncthreads();
        if (c + 1 < NCHUNK) issue_chunk((c + 1) * 32, (c + 1) & 1);

        const uint32_t stg = sb + (c & 1) * STAGEB;
#pragma unroll
        for (int ks = 0; ks < 32; ks += 16) {
            uint32_t bf[2][4];
#pragma unroll
            for (int p = 0; p < 2; p++) {
                int br = wn + p * 16 + (seg >> 1) * 8 + lrow;
                int bc = ks + (seg & 1) * 8;
                uint32_t off = (uint32_t)(br * SKB + bc) * 2;
                ldsm_x4(bf[p], stg + 2 * TILEB + off);
            }
#pragma unroll
            for (int mt = 0; mt < 4; mt++) {
                int ar = wm + mt * 16 + (seg & 1) * 8 + lrow;
                int ac = ks + (seg >> 1) * 8;
                uint32_t off = (uint32_t)(ar * SKB + ac) * 2;
                uint32_t ah[4], al[4];
                ldsm_x4(ah, stg + 0 * TILEB + off);
                ldsm_x4(al, stg + 1 * TILEB + off);
#pragma unroll
                for (int nt = 0; nt < 4; nt++) {
                    int p = nt >> 1, q = (nt & 1) * 2;
                    mma_f16(acc[mt][nt], ah, bf[p][q], bf[p][q + 1]);
                    mma_f16(acc[mt][nt], al, bf[p][q], bf[p][q + 1]);
                }
            }
        }
        __syncthreads();
    }

    const int trow = lane >> 2;
    const int tcol = (lane & 3) * 2;

    if (!FS) {
#pragma unroll
        for (int mt = 0; mt < 4; mt++) {
#pragma unroll
            for (int nt = 0; nt < 4; nt++) {
                size_t r0 = (size_t)(bm + wm + mt * 16 + trow);
                size_t cc = (size_t)(bn + wn + nt * 8 + tcol);
                *(float2*)(C0 + r0 * DIM + cc) =
                    make_float2(acc[mt][nt][0], acc[mt][nt][1]);
                *(float2*)(C0 + (r0 + 8) * DIM + cc) =
                    make_float2(acc[mt][nt][2], acc[mt][nt][3]);
            }
        }
    } else {
        __nv_bfloat16* Hp = (z == 0) ? H0 : (z == 1 ? H1 : H2);
        __nv_bfloat16* Lp = (z == 0) ? L0 : (z == 1 ? L1 : L2);
        const bool rope = (z != 2);
#pragma unroll
        for (int nt = 0; nt < 4; nt++) {
            int cc = bn + wn + nt * 8 + tcol;
            float invf = 0.0f;
            if (rope) {
                int j = (cc & 63) >> 1;
                invf = 1.0f / powf(10000.0f, (float)(2 * j) * (1.0f / 64.0f));
            }
#pragma unroll
            for (int mt = 0; mt < 4; mt++) {
                int r0 = bm + wm + mt * 16 + trow;
                float a0 = acc[mt][nt][0], a1 = acc[mt][nt][1];
                float a2 = acc[mt][nt][2], a3 = acc[mt][nt][3];
                if (rope) {
                    float s0, c0, s1, c1;
                    sincosf((float)r0 * invf, &s0, &c0);
                    sincosf((float)(r0 + 8) * invf, &s1, &c1);
                    float n0 = a0 * c0 - a1 * s0;
                    float n1 = a0 * s0 + a1 * c0;
                    float n2 = a2 * c1 - a3 * s1;
                    float n3 = a2 * s1 + a3 * c1;
                    a0 = n0; a1 = n1; a2 = n2; a3 = n3;
                }
                uint32_t hw0, lw0, hw1, lw1;
                split_pair_bf(a0, a1, hw0, lw0);
                split_pair_bf(a2, a3, hw1, lw1);
                size_t base0 = (size_t)r0 * DIM + cc;
                size_t base1 = (size_t)(r0 + 8) * DIM + cc;
                *(uint32_t*)(Hp + base0) = hw0;
                *(uint32_t*)(Lp + base0) = lw0;
                *(uint32_t*)(Hp + base1) = hw1;
                *(uint32_t*)(Lp + base1) = lw1;
            }
        }
    }
}

// ---------------- HMMA split-bf16 sliding-window flash attention -----------
#define SKD 72
#define ATN_Q_HI 0
#define ATN_Q_LO 18432
#define ATN_K_HI 36864
#define ATN_K_LO 55296
#define ATN_V_HI 73728
#define ATN_V_LO 92160
#define ATN_SMEM 110592

__global__ __launch_bounds__(256, 1) void attn_hmma(
    const __nv_bfloat16* __restrict__ qhi, const __nv_bfloat16* __restrict__ qlo,
    const __nv_bfloat16* __restrict__ khi, const __nv_bfloat16* __restrict__ klo,
    const __nv_bfloat16* __restrict__ vhi, const __nv_bfloat16* __restrict__ vlo,
    __half* __restrict__ ohi, __half* __restrict__ olo)
{
    extern __shared__ char sms[];
    const uint32_t sb = smem_u32(sms);
    const int t = threadIdx.x;
    const int lane = t & 31;
    const int wid  = t >> 5;
    const int h  = blockIdx.y;
    const int qs = blockIdx.x * 128;
    const int lrow = lane & 7;
    const int seg  = lane >> 3;

#pragma unroll
    for (int i = 0; i < 4; i++) {
        int f = i * 256 + t;
        int r = f >> 3, cg = (f & 7) * 8;
        uint32_t so = (uint32_t)(r * SKD + cg) * 2;
        size_t g = (size_t)(qs + r) * DIM + h * HD + cg;
        *(uint4*)(sms + ATN_Q_HI + so) = *(const uint4*)(qhi + g);
        *(uint4*)(sms + ATN_Q_LO + so) = *(const uint4*)(qlo + g);
    }
    __syncthreads();

    uint32_t aQh[4][4], aQl[4][4];
    {
        int ar = wid * 16 + (seg & 1) * 8 + lrow;
#pragma unroll
        for (int ks = 0; ks < 4; ks++) {
            int ac = ks * 16 + (seg >> 1) * 8;
            uint32_t off = (uint32_t)(ar * SKD + ac) * 2;
            ldsm_x4(aQh[ks], sb + ATN_Q_HI + off);
            ldsm_x4(aQl[ks], sb + ATN_Q_LO + off);
        }
    }

    float m0 = -1e30f, m1 = -1e30f, l0 = 0.0f, l1 = 0.0f;
    float oa[8][4];
#pragma unroll
    for (int i = 0; i < 8; i++)
#pragma unroll
        for (int j = 0; j < 4; j++) oa[i][j] = 0.0f;

    const int r0 = wid * 16 + (lane >> 2);
    const int qg0 = qs + r0;
    const int qg1 = qg0 + 8;

    int kt0 = qs - WIN;
    if (kt0 < 0) kt0 = 0;

    for (int kt = kt0; kt <= qs; kt += 128) {
        __syncthreads();
#pragma unroll
        for (int i = 0; i < 4; i++) {
            int f = i * 256 + t;
            int r = f >> 3, cg = (f & 7) * 8;
            uint32_t so = (uint32_t)(r * SKD + cg) * 2;
            size_t g = (size_t)(kt + r) * DIM + h * HD + cg;
            *(uint4*)(sms + ATN_K_HI + so) = *(const uint4*)(khi + g);
            *(uint4*)(sms + ATN_K_LO + so) = *(const uint4*)(klo + g);
            *(uint4*)(sms + ATN_V_HI + so) = *(const uint4*)(vhi + g);
            *(uint4*)(sms + ATN_V_LO + so) = *(const uint4*)(vlo + g);
        }
        __syncthreads();

        float sc[16][4];
#pragma unroll
        for (int i = 0; i < 16; i++)
#pragma unroll
            for (int j = 0; j < 4; j++) sc[i][j] = 0.0f;

#pragma unroll
        for (int ks = 0; ks < 4; ks++) {
#pragma unroll
            for (int bp = 0; bp < 8; bp++) {
                uint32_t bh[4], bl[4];
                int br = bp * 16 + (seg >> 1) * 8 + lrow;
                int bc = ks * 16 + (seg & 1) * 8;
                uint32_t off = (uint32_t)(br * SKD + bc) * 2;
                ldsm_x4(bh, sb + ATN_K_HI + off);
                ldsm_x4(bl, sb + ATN_K_LO + off);
                mma_bf16(sc[2 * bp],     aQh[ks], bh[0], bh[1]);
                mma_bf16(sc[2 * bp],     aQh[ks], bl[0], bl[1]);
                mma_bf16(sc[2 * bp],     aQl[ks], bh[0], bh[1]);
                mma_bf16(sc[2 * bp + 1], aQh[ks], bh[2], bh[3]);
                mma_bf16(sc[2 * bp + 1], aQh[ks], bl[2], bl[3]);
                mma_bf16(sc[2 * bp + 1], aQl[ks], bh[2], bh[3]);
            }
        }

        float nm0 = m0, nm1 = m1;
#pragma unroll
        for (int nt = 0; nt < 16; nt++) {
            int kg = kt + nt * 8 + (lane & 3) * 2;
            sc[nt][0] = (kg     <= qg0 && kg     > qg0 - WIN) ? sc[nt][0] * 0.125f : -1e30f;
            sc[nt][1] = (kg + 1 <= qg0 && kg + 1 > qg0 - WIN) ? sc[nt][1] * 0.125f : -1e30f;
            sc[nt][2] = (kg     <= qg1 && kg     > qg1 - WIN) ? sc[nt][2] * 0.125f : -1e30f;
            sc[nt][3] = (kg + 1 <= qg1 && kg + 1 > qg1 - WIN) ? sc[nt][3] * 0.125f : -1e30f;
            nm0 = fmaxf(nm0, fmaxf(sc[nt][0], sc[nt][1]));
            nm1 = fmaxf(nm1, fmaxf(sc[nt][2], sc[nt][3]));
        }
        nm0 = fmaxf(nm0, __shfl_xor_sync(0xffffffffu, nm0, 1));
        nm0 = fmaxf(nm0, __shfl_xor_sync(0xffffffffu, nm0, 2));
        nm1 = fmaxf(nm1, __shfl_xor_sync(0xffffffffu, nm1, 1));
        nm1 = fmaxf(nm1, __shfl_xor_sync(0xffffffffu, nm1, 2));

        float al0 = __expf(m0 - nm0);
        float al1 = __expf(m1 - nm1);
        m0 = nm0; m1 = nm1;

        float rs0 = 0.0f, rs1 = 0.0f;
#pragma unroll
        for (int nt = 0; nt < 16; nt++) {
            float p0 = (sc[nt][0] > -1e29f) ? __expf(sc[nt][0] - m0) : 0.0f;
            float p1 = (sc[nt][1] > -1e29f) ? __expf(sc[nt][1] - m0) : 0.0f;
            float p2 = (sc[nt][2] > -1e29f) ? __expf(sc[nt][2] - m1) : 0.0f;
            float p3 = (sc[nt][3] > -1e29f) ? __expf(sc[nt][3] - m1) : 0.0f;
            sc[nt][0] = p0; sc[nt][1] = p1; sc[nt][2] = p2; sc[nt][3] = p3;
            rs0 += p0 + p1;
            rs1 += p2 + p3;
        }
        rs0 += __shfl_xor_sync(0xffffffffu, rs0, 1);
        rs0 += __shfl_xor_sync(0xffffffffu, rs0, 2);
        rs1 += __shfl_xor_sync(0xffffffffu, rs1, 1);
        rs1 += __shfl_xor_sync(0xffffffffu, rs1, 2);
        l0 = l0 * al0 + rs0;
        l1 = l1 * al1 + rs1;

#pragma unroll
        for (int i = 0; i < 8; i++) {
            oa[i][0] *= al0; oa[i][1] *= al0;
            oa[i][2] *= al1; oa[i][3] *= al1;
        }

#pragma unroll
        for (int j = 0; j < 8; j++) {
            float p00 = sc[2 * j][0],     p01 = sc[2 * j][1];
            float p02 = sc[2 * j][2],     p03 = sc[2 * j][3];
            float p10 = sc[2 * j + 1][0], p11 = sc[2 * j + 1][1];
            float p12 = sc[2 * j + 1][2], p13 = sc[2 * j + 1][3];
            uint32_t pah[4], pal[4];
            split_pair_bf(p00, p01, pah[0], pal[0]);
            split_pair_bf(p02, p03, pah[1], pal[1]);
            split_pair_bf(p10, p11, pah[2], pal[2]);
            split_pair_bf(p12, p13, pah[3], pal[3]);
#pragma unroll
            for (int dp = 0; dp < 4; dp++) {
                uint32_t bh[4], bl[4];
                int kk = j * 16 + (seg & 1) * 8 + lrow;
                int nn = dp * 16 + (seg >> 1) * 8;
                uint32_t off = (uint32_t)(kk * SKD + nn) * 2;
                ldsm_x4_trans(bh, sb + ATN_V_HI + off);
                ldsm_x4_trans(bl, sb + ATN_V_LO + off);
                mma_bf16(oa[dp * 2],     pah, bh[0], bh[1]);
                mma_bf16(oa[dp * 2],     pah, bl[0], bl[1]);
                mma_bf16(oa[dp * 2],     pal, bh[0], bh[1]);
                mma_bf16(oa[dp * 2 + 1], pah, bh[2], bh[3]);
                mma_bf16(oa[dp * 2 + 1], pah, bl[2], bl[3]);
                mma_bf16(oa[dp * 2 + 1], pal, bh[2], bh[3]);
            }
        }
    }

    // Epilogue: normalize + fused fp16 hi/lo split (for final GEMM)
    float inv0 = 1.0f / l0;
    float inv1 = 1.0f / l1;
    const int tcol = (lane & 3) * 2;
#pragma unroll
    for (int dt = 0; dt < 8; dt++) {
        size_t c = (size_t)(h * HD + dt * 8 + tcol);
        uint32_t hw0, lw0, hw1, lw1;
        split_pair_h(oa[dt][0] * inv0, oa[dt][1] * inv0, hw0, lw0);
        split_pair_h(oa[dt][2] * inv1, oa[dt][3] * inv1, hw1, lw1);
        size_t b0 = (size_t)qg0 * DIM + c;
        size_t b1 = (size_t)qg1 * DIM + c;
        *(uint32_t*)(ohi + b0) = hw0;
        *(uint32_t*)(olo + b0) = lw0;
        *(uint32_t*)(ohi + b1) = hw1;
        *(uint32_t*)(olo + b1) = lw1;
    }
}

// ---------------------------------------------------------------------------
extern "C" void kernel_launch(void* const* d_in, const int* in_sizes, int n_in,
                              void* d_out, int out_size)
{
    const float* x  = (const float*)d_in[0];
    const float* Wq = (const float*)d_in[1];
    const float* Wk = (const float*)d_in[2];
    const float* Wv = (const float*)d_in[3];
    const float* Wo = (const float*)d_in[4];
    float* out = (float*)d_out;

    __half *xhi, *xlo, *w, *ohi, *olo;
    __nv_bfloat16 *qhi, *qlo, *khi, *klo, *vhi, *vlo;
    cudaGetSymbolAddress((void**)&xhi, g_xhi);
    cudaGetSymbolAddress((void**)&xlo, g_xlo);
    cudaGetSymbolAddress((void**)&w,   g_w);
    cudaGetSymbolAddress((void**)&qhi, g_qhi);
    cudaGetSymbolAddress((void**)&qlo, g_qlo);
    cudaGetSymbolAddress((void**)&khi, g_khi);
    cudaGetSymbolAddress((void**)&klo, g_klo);
    cudaGetSymbolAddress((void**)&vhi, g_vhi);
    cudaGetSymbolAddress((void**)&vlo, g_vlo);
    cudaGetSymbolAddress((void**)&ohi, g_ohi);
    cudaGetSymbolAddress((void**)&olo, g_olo);

    cudaFuncSetAttribute(gemm_hmma<true>,
                         cudaFuncAttributeMaxDynamicSharedMemorySize, GEMM_SMEM);
    cudaFuncSetAttribute(gemm_hmma<false>,
                         cudaFuncAttributeMaxDynamicSharedMemorySize, GEMM_SMEM);
    cudaFuncSetAttribute(attn_hmma,
                         cudaFuncAttributeMaxDynamicSharedMemorySize, ATN_SMEM);

    // 1) Fused split: x -> fp16 hi/lo, weights -> fp16 (single launch)
    {
        int total = XN4 + 4 * WN4;
        split_all_kernel<<<(total + 255) / 256, 256>>>(
            x, Wq, Wk, Wv, Wo, xhi, xlo, w);
    }

    // 2) Fused Q/K/V projections + RoPE + bf16 split (fp16 2-term GEMM)
    gemm_hmma<true><<<dim3(DIM / 128, S_LEN / 128, 3), 256, GEMM_SMEM>>>(
        xhi, xlo, w, nullptr,
        qhi, qlo, khi, klo, vhi, vlo);

    // 3) Sliding-window attention (bf16 3-term, fused fp16 output split)
    attn_hmma<<<dim3(S_LEN / 128, NH), 256, ATN_SMEM>>>(
        qhi, qlo, khi, klo, vhi, vlo, ohi, olo);

    // 4) Output projection (fp16 2-term GEMM, fp32 out)
    gemm_hmma<false><<<dim3(DIM / 128, S_LEN / 128, 1), 256, GEMM_SMEM>>>(
        ohi, olo, w + 3 * (size_t)DIM * DIM, out,
        nullptr, nullptr, nullptr, nullptr, nullptr, nullptr);
}